// round 9
// baseline (speedup 1.0000x reference)
#include <cuda_runtime.h>
#include <cuda_bf16.h>
#include <cstdint>
#include <stddef.h>

#define B_  32
#define T_  1024
#define D_  2048
#define U_  1024
#define M_  (B_*T_)
#define NKC 64                 // k-chunks of 32 elems

// ---- score kernel dynamic smem layout (offsets from 1024-aligned base) ----
// 3 stages x (A 16KB + B 32KB) = 147456
#define STG_SZ   49152
#define OFF_BQ   16384         // B within stage
#define OFF_QADD 147456        // 256 floats
#define OFF_VV   148480        // 256 floats
#define OFF_RED  149504        // 128x4 floats
#define SMEM_REQ 152576        // 151552 + align slack

// ---- scratch globals (no device allocs allowed) ----
__device__ unsigned char g_Asw[(size_t)256*NKC*16384]; // 256MB pre-split values (bf16 hi|lo)
__device__ unsigned char g_Bsw[(size_t)4*NKC*32768];   // 8MB pre-split W1 image
__device__ float g_qpart[8*B_*U_];
__device__ float g_spart[4*M_];
__device__ float g_ctxpart[4*(size_t)B_*D_];

// ============================ helpers ============================
__device__ __forceinline__ uint32_t smem_u32(const void* p) {
    uint32_t a;
    asm("{ .reg .u64 t; cvta.to.shared.u64 t, %1; cvt.u32.u64 %0, t; }" : "=r"(a) : "l"(p));
    return a;
}
__device__ __forceinline__ float fast_tanh(float x) {
    float y; asm("tanh.approx.f32 %0, %1;" : "=f"(y) : "f"(x)); return y;
}
__device__ __forceinline__ unsigned pack_bf2(float a, float b) {
    __nv_bfloat16 ha = __float2bfloat16(a), hb = __float2bfloat16(b);
    return (unsigned)__bfloat16_as_ushort(ha) | ((unsigned)__bfloat16_as_ushort(hb) << 16);
}
__device__ __forceinline__ void split_pack(float a, float b, unsigned& hi, unsigned& lo) {
    __nv_bfloat16 ha = __float2bfloat16(a), hb = __float2bfloat16(b);
    hi = (unsigned)__bfloat16_as_ushort(ha) | ((unsigned)__bfloat16_as_ushort(hb) << 16);
    lo = pack_bf2(a - __bfloat162float(ha), b - __bfloat162float(hb));
}
__device__ __forceinline__ void cp_async16(uint32_t dst, const void* src) {
    asm volatile("cp.async.cg.shared.global [%0], [%1], 16;" :: "r"(dst), "l"(src));
}
#define CP_COMMIT() asm volatile("cp.async.commit_group;" ::: "memory")
#define CP_WAIT1()  asm volatile("cp.async.wait_group 1;" ::: "memory")
#define CP_WAIT0()  asm volatile("cp.async.wait_group 0;" ::: "memory")
#define LDSM4(r, addr) \
    asm volatile("ldmatrix.sync.aligned.m8n8.x4.shared.b16 {%0,%1,%2,%3}, [%4];" \
                 : "=r"((r)[0]), "=r"((r)[1]), "=r"((r)[2]), "=r"((r)[3]) : "r"(addr))
#define MMA16816(d, a, b0, b1) \
    asm volatile("mma.sync.aligned.m16n8k16.row.col.f32.bf16.bf16.f32 " \
                 "{%0,%1,%2,%3}, {%4,%5,%6,%7}, {%8,%9}, {%0,%1,%2,%3};" \
                 : "+f"((d)[0]), "+f"((d)[1]), "+f"((d)[2]), "+f"((d)[3]) \
                 : "r"((a)[0]), "r"((a)[1]), "r"((a)[2]), "r"((a)[3]), "r"(b0), "r"(b1))

// ---------------------------------------------------------------------------
// K0a: pre-split values -> g_Asw[mb 256][kc 64][16KB tile]
// tile row r (0..127) = 128B linear: [hi k0..31 | lo k0..31] bf16.
// grid (256, 64), 256 threads. Fully coalesced both sides.
// ---------------------------------------------------------------------------
__global__ void asplit_kernel(const float* __restrict__ values) {
    const int mb = blockIdx.x, kc = blockIdx.y, tid = threadIdx.x;
    const int r = tid >> 1, h = tid & 1;             // 2 threads/row, 16 elems each
    const float4* src = (const float4*)(values + (size_t)(mb*128 + r)*D_ + kc*32 + h*16);
    float4 f0 = src[0], f1 = src[1], f2 = src[2], f3 = src[3];
    float fv[16] = {f0.x,f0.y,f0.z,f0.w, f1.x,f1.y,f1.z,f1.w,
                    f2.x,f2.y,f2.z,f2.w, f3.x,f3.y,f3.z,f3.w};
    unsigned hi[8], lo[8];
    #pragma unroll
    for (int i = 0; i < 8; i++) split_pack(fv[2*i], fv[2*i+1], hi[i], lo[i]);
    unsigned char* row = g_Asw + ((size_t)(mb*NKC + kc))*16384 + r*128;
    *(uint4*)(row + (h*2    )*16) = make_uint4(hi[0], hi[1], hi[2], hi[3]);
    *(uint4*)(row + (h*2 + 1)*16) = make_uint4(hi[4], hi[5], hi[6], hi[7]);
    *(uint4*)(row + (4 + h*2)*16) = make_uint4(lo[0], lo[1], lo[2], lo[3]);
    *(uint4*)(row + (5 + h*2)*16) = make_uint4(lo[4], lo[5], lo[6], lo[7]);
}

// ---------------------------------------------------------------------------
// K0b: split+transpose W1 -> g_Bsw[nb 4][kc 64][32KB tile]
// tile row n (0..255) = 128B linear: [hi k0..31 | lo k0..31] bf16.
// grid (4, 64), 256 threads.
// ---------------------------------------------------------------------------
__global__ void w1split_kernel(const float* __restrict__ W1) {
    const int nb = blockIdx.x, kc = blockIdx.y, t = threadIdx.x;
    const int ng = nb*256 + t;
    float v[32];
    #pragma unroll
    for (int j = 0; j < 32; j++)
        v[j] = __ldg(&W1[(size_t)(kc*32 + j)*U_ + ng]);
    unsigned char* dst = g_Bsw + ((size_t)(nb*NKC + kc)*256 + t)*128;
    #pragma unroll
    for (int c = 0; c < 4; c++) {
        unsigned h[4], l[4];
        #pragma unroll
        for (int i = 0; i < 4; i++)
            split_pack(v[c*8 + 2*i], v[c*8 + 2*i + 1], h[i], l[i]);
        *(uint4*)(dst + c*16)       = make_uint4(h[0], h[1], h[2], h[3]);
        *(uint4*)(dst + (c + 4)*16) = make_uint4(l[0], l[1], l[2], l[3]);
    }
}

// ---------------------------------------------------------------------------
// K1: qproj partials: g_qpart[sl][b][u] = sum_{d in 256-slice} q[b,d]*W2[d,u] (+b2@sl0)
// ---------------------------------------------------------------------------
__global__ void qproj_part_kernel(const float* __restrict__ query,
                                  const float* __restrict__ W2,
                                  const float* __restrict__ b2) {
    const int b = blockIdx.x, sl = blockIdx.y;
    const int u4 = threadIdx.x;
    float4 acc = (sl == 0) ? *(const float4*)&b2[u4*4] : make_float4(0.f,0.f,0.f,0.f);
    const float* q = query + (size_t)b * D_;
    const int d0 = sl * 256;
    #pragma unroll 8
    for (int d = d0; d < d0 + 256; d++) {
        float  qd = __ldg(&q[d]);
        float4 w  = *(const float4*)&W2[(size_t)d*U_ + u4*4];
        acc.x += qd*w.x; acc.y += qd*w.y; acc.z += qd*w.z; acc.w += qd*w.w;
    }
    *(float4*)&g_qpart[(size_t)(sl*B_ + b)*U_ + u4*4] = acc;
}

// ---------------------------------------------------------------------------
// K2: fused bf16x3 HMMA GEMM + tanh + dot-V -> g_spart[nb][m]
// grid (256 mblk, 4 nblk), 512 threads (16 warps, 4m x 4n, warp tile 32x64).
// Pure cp.async 3-stage pipeline, ONE barrier per k-chunk, no in-loop convert.
// ---------------------------------------------------------------------------
__global__ __launch_bounds__(512, 1)
void score_kernel(const float* __restrict__ b1,
                  const float* __restrict__ Vvec) {
    extern __shared__ char smraw[];
    const uint32_t rb   = smem_u32(smraw);
    const uint32_t base = (rb + 1023u) & ~1023u;
    char* sm = smraw + (base - rb);

    const int tid = threadIdx.x;
    const int wid = tid >> 5, ln = tid & 31;
    const int wm  = wid >> 2, wn = wid & 3;
    const int mb  = blockIdx.x, nb = blockIdx.y;
    const int m0  = mb * 128, n0 = nb * 256;
    const int b   = m0 >> 10;

    float* qadd_s = (float*)(sm + OFF_QADD);
    float* vv_s   = (float*)(sm + OFF_VV);
    float* red    = (float*)(sm + OFF_RED);

    if (tid < 256) {
        const int n = n0 + tid;
        float s = __ldg(&b1[n]);
        #pragma unroll
        for (int sl = 0; sl < 8; sl++) s += g_qpart[(size_t)(sl*B_ + b)*U_ + n];
        qadd_s[tid] = s;
        vv_s[tid]   = __ldg(&Vvec[n]);
    }

    const unsigned char* atiles = g_Asw + (size_t)mb*NKC*16384;
    const unsigned char* btiles = g_Bsw + (size_t)nb*NKC*32768;

    // fill: B 2048x16B + A 1024x16B; swizzle (^ row&7 on chunk) applied at dst.
    #define STAGE_FILL(stg, kc) do {                                              \
        const unsigned char* bt = btiles + (size_t)(kc)*32768;                    \
        const uint32_t bdst = base + (stg)*STG_SZ + OFF_BQ;                       \
        _Pragma("unroll")                                                         \
        for (int i = 0; i < 4; i++) {                                             \
            int g = tid + i*512;                                                  \
            int r = g >> 3, c = g & 7;                                            \
            cp_async16(bdst + r*128 + ((c ^ (r & 7))*16), bt + (size_t)g*16);     \
        }                                                                         \
        const unsigned char* at = atiles + (size_t)(kc)*16384;                    \
        const uint32_t adst = base + (stg)*STG_SZ;                                \
        _Pragma("unroll")                                                         \
        for (int i = 0; i < 2; i++) {                                             \
            int g = tid + i*512;                                                  \
            int r = g >> 3, c = g & 7;                                            \
            cp_async16(adst + r*128 + ((c ^ (r & 7))*16), at + (size_t)g*16);     \
        }                                                                         \
    } while (0)

    float acc[2][8][4];
    #pragma unroll
    for (int i = 0; i < 2; i++)
        #pragma unroll
        for (int j = 0; j < 8; j++)
            #pragma unroll
            for (int q = 0; q < 4; q++) acc[i][j][q] = 0.f;

    const uint32_t sxs  = (uint32_t)(ln & 7) * 16;
    const uint32_t khfA = (uint32_t)(ln >> 4);
    const uint32_t khfB = (uint32_t)((ln >> 3) & 1);
    uint32_t rA[2], rB[4];
    #pragma unroll
    for (int mi = 0; mi < 2; mi++)
        rA[mi] = (uint32_t)(wm*32 + mi*16 + (ln & 15)) * 128;
    #pragma unroll
    for (int nt = 0; nt < 4; nt++)
        rB[nt] = (uint32_t)(wn*64 + nt*16 + (ln & 7) + ((ln >> 4) << 3)) * 128;

    STAGE_FILL(0, 0); CP_COMMIT();
    STAGE_FILL(1, 1); CP_COMMIT();

    int s3 = 0;                       // kc % 3
    for (int kc = 0; kc < NKC; kc++) {
        if (kc + 1 < NKC) CP_WAIT1(); else CP_WAIT0();
        __syncthreads();

        // prefetch next stage immediately (its prior readers are past the barrier)
        if (kc + 2 < NKC) {
            int f3 = s3 + 2; if (f3 >= 3) f3 -= 3;
            STAGE_FILL(f3, kc + 2); CP_COMMIT();
        }

        const uint32_t A0 = base + s3*STG_SZ;
        const uint32_t B0 = A0 + OFF_BQ;
        #pragma unroll
        for (int s = 0; s < 2; s++) {
            uint32_t ah[2][4], al[2][4], bfr[4][4];
            const uint32_t cAh = (((uint32_t)s*2 + khfA)     * 16) ^ sxs;
            const uint32_t cAl = (((uint32_t)s*2 + khfA + 4) * 16) ^ sxs;
            #pragma unroll
            for (int mi = 0; mi < 2; mi++) {
                LDSM4(ah[mi], A0 + rA[mi] + cAh);
                LDSM4(al[mi], A0 + rA[mi] + cAl);
            }
            const uint32_t cBh = (((uint32_t)s*2 + khfB)     * 16) ^ sxs;
            const uint32_t cBl = (((uint32_t)s*2 + khfB + 4) * 16) ^ sxs;
            #pragma unroll
            for (int nt = 0; nt < 4; nt++) LDSM4(bfr[nt], B0 + rB[nt] + cBh);
            #pragma unroll
            for (int mi = 0; mi < 2; mi++)
                #pragma unroll
                for (int nt = 0; nt < 4; nt++) {
                    MMA16816(acc[mi][2*nt],   ah[mi], bfr[nt][0], bfr[nt][1]); // hi*hi
                    MMA16816(acc[mi][2*nt+1], ah[mi], bfr[nt][2], bfr[nt][3]);
                    MMA16816(acc[mi][2*nt],   al[mi], bfr[nt][0], bfr[nt][1]); // lo*hi
                    MMA16816(acc[mi][2*nt+1], al[mi], bfr[nt][2], bfr[nt][3]);
                }
            #pragma unroll
            for (int nt = 0; nt < 4; nt++) LDSM4(bfr[nt], B0 + rB[nt] + cBl);
            #pragma unroll
            for (int mi = 0; mi < 2; mi++)
                #pragma unroll
                for (int nt = 0; nt < 4; nt++) {
                    MMA16816(acc[mi][2*nt],   ah[mi], bfr[nt][0], bfr[nt][1]); // hi*lo
                    MMA16816(acc[mi][2*nt+1], ah[mi], bfr[nt][2], bfr[nt][3]);
                }
        }
        if (++s3 >= 3) s3 -= 3;
    }

    // ---- epilogue: tanh(c + qadd)*V folded into per-row partials ----
    float racc[4] = {0.f, 0.f, 0.f, 0.f};
    #pragma unroll
    for (int mi = 0; mi < 2; mi++)
        #pragma unroll
        for (int nj = 0; nj < 8; nj++) {
            const int nc = wn*64 + nj*8 + 2*(ln & 3);
            const float q0 = qadd_s[nc],   v0 = vv_s[nc];
            const float q1 = qadd_s[nc+1], v1 = vv_s[nc+1];
            const float* d = acc[mi][nj];
            racc[mi*2]   += fast_tanh(d[0] + q0)*v0 + fast_tanh(d[1] + q1)*v1;
            racc[mi*2+1] += fast_tanh(d[2] + q0)*v0 + fast_tanh(d[3] + q1)*v1;
        }
    #pragma unroll
    for (int off = 1; off <= 2; off <<= 1)
        #pragma unroll
        for (int i = 0; i < 4; i++)
            racc[i] += __shfl_xor_sync(0xffffffffu, racc[i], off);

    if ((ln & 3) == 0) {
        #pragma unroll
        for (int mi = 0; mi < 2; mi++)
            #pragma unroll
            for (int h = 0; h < 2; h++) {
                const int row = wm*32 + mi*16 + (ln >> 2) + 8*h;
                red[row*4 + wn] = racc[mi*2 + h];
            }
    }
    __syncthreads();
    if (tid < 128)
        g_spart[(size_t)nb*M_ + m0 + tid] =
            red[tid*4] + red[tid*4+1] + red[tid*4+2] + red[tid*4+3];
}

// ---------------------------------------------------------------------------
// K3: softmax over T per batch (sums the 4 n-block score partials).
// ---------------------------------------------------------------------------
__global__ void softmax_kernel(float* __restrict__ out_w) {
    __shared__ float sh[32];
    __shared__ float bcast;
    const int b = blockIdx.x, t = threadIdx.x;
    const int lane = t & 31, wd = t >> 5;
    const size_t idx = (size_t)b*T_ + t;

    float s = g_spart[idx] + g_spart[M_ + idx] + g_spart[2*(size_t)M_ + idx]
            + g_spart[3*(size_t)M_ + idx];

    float m = s;
    #pragma unroll
    for (int o = 16; o; o >>= 1) m = fmaxf(m, __shfl_xor_sync(0xffffffffu, m, o));
    if (lane == 0) sh[wd] = m;
    __syncthreads();
    if (wd == 0) {
        float mm = sh[lane];
        #pragma unroll
        for (int o = 16; o; o >>= 1) mm = fmaxf(mm, __shfl_xor_sync(0xffffffffu, mm, o));
        if (lane == 0) bcast = mm;
    }
    __syncthreads();
    const float mx = bcast;

    float e = __expf(s - mx);
    float sum = e;
    #pragma unroll
    for (int o = 16; o; o >>= 1) sum += __shfl_xor_sync(0xffffffffu, sum, o);
    __syncthreads();
    if (lane == 0) sh[wd] = sum;
    __syncthreads();
    if (wd == 0) {
        float ss = sh[lane];
        #pragma unroll
        for (int o = 16; o; o >>= 1) ss += __shfl_xor_sync(0xffffffffu, ss, o);
        if (lane == 0) bcast = ss;
    }
    __syncthreads();
    out_w[idx] = e / bcast;
}

// ---------------------------------------------------------------------------
// K4: context partials over t-slices of 256; grid (8, 4, 32), 256 threads.
// ---------------------------------------------------------------------------
__global__ void context_part_kernel(const float* __restrict__ values,
                                    const float* __restrict__ w) {
    __shared__ float ws[256];
    const int dc = blockIdx.x, ts = blockIdx.y, b = blockIdx.z;
    const int d  = dc*256 + threadIdx.x;
    ws[threadIdx.x] = w[(size_t)b*T_ + ts*256 + threadIdx.x];
    __syncthreads();
    const float* vp = values + ((size_t)b*T_ + ts*256)*D_ + d;
    float acc = 0.f;
    #pragma unroll 8
    for (int t = 0; t < 256; t++)
        acc += ws[t] * vp[(size_t)t*D_];
    g_ctxpart[(size_t)(ts*B_ + b)*D_ + d] = acc;
}

__global__ void context_reduce_kernel(float* __restrict__ ctx) {
    const size_t i = (size_t)blockIdx.x*256 + threadIdx.x;
    ctx[i] = g_ctxpart[i] + g_ctxpart[(size_t)B_*D_ + i]
           + g_ctxpart[(size_t)2*B_*D_ + i] + g_ctxpart[(size_t)3*B_*D_ + i];
}

// ---------------------------------------------------------------------------
extern "C" void kernel_launch(void* const* d_in, const int* in_sizes, int n_in,
                              void* d_out, int out_size) {
    const float* query  = (const float*)d_in[0];
    const float* values = (const float*)d_in[1];
    const float* W1     = (const float*)d_in[2];
    const float* b1     = (const float*)d_in[3];
    const float* W2     = (const float*)d_in[4];
    const float* b2     = (const float*)d_in[5];
    const float* V      = (const float*)d_in[6];
    // bv (d_in[7]) shifts all scores equally: softmax-invariant, outputs unaffected.

    float* out = (float*)d_out;
    float* ctx = out;                   // (B, D)
    float* w   = out + B_*D_;           // (B, T, 1)

    cudaFuncSetAttribute(score_kernel, cudaFuncAttributeMaxDynamicSharedMemorySize, SMEM_REQ);

    asplit_kernel       <<<dim3(256, 64),  256>>>(values);
    w1split_kernel      <<<dim3(4, 64),    256>>>(W1);
    qproj_part_kernel   <<<dim3(B_, 8),    256>>>(query, W2, b2);
    score_kernel        <<<dim3(256, 4), 512, SMEM_REQ>>>(b1, V);
    softmax_kernel      <<<B_,             T_ >>>(w);
    context_part_kernel <<<dim3(8, 4, B_), 256>>>(values, w);
    context_reduce_kernel<<<(B_*D_)/256,   256>>>(ctx);
}

// round 11
// speedup vs baseline: 1.4823x; 1.4823x over previous
#include <cuda_runtime.h>
#include <cuda_bf16.h>
#include <cstdint>
#include <stddef.h>

#define B_  32
#define T_  1024
#define D_  2048
#define U_  1024
#define M_  (B_*T_)
#define NKC 64                 // k-chunks of 32 elems

// ---- score kernel dynamic smem layout (offsets from 1024-aligned base) ----
// 3 stages x (fp32A 18432 + bf16A 16384 + B 32768) = 202752
#define STG_SZ    67584
#define OFF_BFA   18432        // bf16 A within stage
#define OFF_BQ    34816        // B within stage
#define OFF_QADD  202752       // 256 floats
#define OFF_VV    203776       // 256 floats
#define OFF_RED   204800       // 128x4 floats
#define SMEM_REQ  207872       // 206848 + align slack

// ---- scratch globals (no device allocs allowed) ----
__device__ unsigned char g_Bsw[(size_t)4*NKC*32768];   // 8MB pre-split/swizzled W1 image
__device__ float g_qpart[8*B_*U_];
__device__ float g_spart[4*M_];
__device__ float g_ctxpart[4*(size_t)B_*D_];

// ============================ helpers ============================
__device__ __forceinline__ uint32_t smem_u32(const void* p) {
    uint32_t a;
    asm("{ .reg .u64 t; cvta.to.shared.u64 t, %1; cvt.u32.u64 %0, t; }" : "=r"(a) : "l"(p));
    return a;
}
__device__ __forceinline__ float fast_tanh(float x) {
    float y; asm("tanh.approx.f32 %0, %1;" : "=f"(y) : "f"(x)); return y;
}
__device__ __forceinline__ unsigned pack_bf2(float a, float b) {
    __nv_bfloat16 ha = __float2bfloat16(a), hb = __float2bfloat16(b);
    return (unsigned)__bfloat16_as_ushort(ha) | ((unsigned)__bfloat16_as_ushort(hb) << 16);
}
__device__ __forceinline__ void split_pack(float a, float b, unsigned& hi, unsigned& lo) {
    __nv_bfloat16 ha = __float2bfloat16(a), hb = __float2bfloat16(b);
    hi = (unsigned)__bfloat16_as_ushort(ha) | ((unsigned)__bfloat16_as_ushort(hb) << 16);
    lo = pack_bf2(a - __bfloat162float(ha), b - __bfloat162float(hb));
}
__device__ __forceinline__ void cp_async16(uint32_t dst, const void* src) {
    asm volatile("cp.async.cg.shared.global [%0], [%1], 16;" :: "r"(dst), "l"(src));
}
#define CP_COMMIT() asm volatile("cp.async.commit_group;" ::: "memory")
#define CP_WAIT1()  asm volatile("cp.async.wait_group 1;" ::: "memory")
#define CP_WAIT0()  asm volatile("cp.async.wait_group 0;" ::: "memory")
#define STS128(addr, r0, r1, r2, r3) \
    asm volatile("st.shared.v4.b32 [%0], {%1,%2,%3,%4};" \
                 :: "r"(addr), "r"(r0), "r"(r1), "r"(r2), "r"(r3) : "memory")
#define LDSM4(r, addr) \
    asm volatile("ldmatrix.sync.aligned.m8n8.x4.shared.b16 {%0,%1,%2,%3}, [%4];" \
                 : "=r"((r)[0]), "=r"((r)[1]), "=r"((r)[2]), "=r"((r)[3]) : "r"(addr))
#define MMA16816(d, a, b0, b1) \
    asm volatile("mma.sync.aligned.m16n8k16.row.col.f32.bf16.bf16.f32 " \
                 "{%0,%1,%2,%3}, {%4,%5,%6,%7}, {%8,%9}, {%0,%1,%2,%3};" \
                 : "+f"((d)[0]), "+f"((d)[1]), "+f"((d)[2]), "+f"((d)[3]) \
                 : "r"((a)[0]), "r"((a)[1]), "r"((a)[2]), "r"((a)[3]), "r"(b0), "r"(b1))

// ---------------------------------------------------------------------------
// K0: split+transpose W1 -> g_Bsw[nb 4][kc 64][32KB tile], swizzle pre-applied.
// tile row n (0..255) = 128B: [hi k0..31 | lo k0..31] bf16, chunks XOR (n&7).
// grid (4, 64), 256 threads.
// ---------------------------------------------------------------------------
__global__ void w1split_kernel(const float* __restrict__ W1) {
    const int nb = blockIdx.x, kc = blockIdx.y, t = threadIdx.x;
    const int ng = nb*256 + t;
    float v[32];
    #pragma unroll
    for (int j = 0; j < 32; j++)
        v[j] = __ldg(&W1[(size_t)(kc*32 + j)*U_ + ng]);
    unsigned char* dst = g_Bsw + ((size_t)(nb*NKC + kc)*256 + t)*128;
    const int sx = t & 7;
    #pragma unroll
    for (int c = 0; c < 4; c++) {
        unsigned h[4], l[4];
        #pragma unroll
        for (int i = 0; i < 4; i++)
            split_pack(v[c*8 + 2*i], v[c*8 + 2*i + 1], h[i], l[i]);
        *(uint4*)(dst + ((c     ^ sx)*16)) = make_uint4(h[0], h[1], h[2], h[3]);
        *(uint4*)(dst + (((c+4) ^ sx)*16)) = make_uint4(l[0], l[1], l[2], l[3]);
    }
}

// ---------------------------------------------------------------------------
// K1: qproj partials: g_qpart[sl][b][u] = sum_{d in 256-slice} q[b,d]*W2[d,u] (+b2@sl0)
// ---------------------------------------------------------------------------
__global__ void qproj_part_kernel(const float* __restrict__ query,
                                  const float* __restrict__ W2,
                                  const float* __restrict__ b2) {
    const int b = blockIdx.x, sl = blockIdx.y;
    const int u4 = threadIdx.x;
    float4 acc = (sl == 0) ? *(const float4*)&b2[u4*4] : make_float4(0.f,0.f,0.f,0.f);
    const float* q = query + (size_t)b * D_;
    const int d0 = sl * 256;
    #pragma unroll 8
    for (int d = d0; d < d0 + 256; d++) {
        float  qd = __ldg(&q[d]);
        float4 w  = *(const float4*)&W2[(size_t)d*U_ + u4*4];
        acc.x += qd*w.x; acc.y += qd*w.y; acc.z += qd*w.z; acc.w += qd*w.w;
    }
    *(float4*)&g_qpart[(size_t)(sl*B_ + b)*U_ + u4*4] = acc;
}

// ---------------------------------------------------------------------------
// K2: fused bf16x3 HMMA GEMM + tanh + dot-V -> g_spart[nb][m]
// grid (4 nblk, 256 mblk) -- nb fastest so A-tile siblings are wave-concurrent.
// 512 threads (16 warps, 4m x 4n, warp tile 32x64).
// 3-stage pipeline, ONE barrier per k-chunk, convert runs one chunk ahead.
// ---------------------------------------------------------------------------
__global__ __launch_bounds__(512, 1)
void score_kernel(const float* __restrict__ values,
                  const float* __restrict__ b1,
                  const float* __restrict__ Vvec) {
    extern __shared__ char smraw[];
    const uint32_t rb   = smem_u32(smraw);
    const uint32_t base = (rb + 1023u) & ~1023u;
    char* sm = smraw + (base - rb);

    const int tid = threadIdx.x;
    const int wid = tid >> 5, ln = tid & 31;
    const int wm  = wid >> 2, wn = wid & 3;
    const int nb  = blockIdx.x, mb = blockIdx.y;
    const int m0  = mb * 128, n0 = nb * 256;
    const int b   = m0 >> 10;

    float* qadd_s = (float*)(sm + OFF_QADD);
    float* vv_s   = (float*)(sm + OFF_VV);
    float* red    = (float*)(sm + OFF_RED);

    if (tid < 256) {
        const int n = n0 + tid;
        float s = __ldg(&b1[n]);
        #pragma unroll
        for (int sl = 0; sl < 8; sl++) s += g_qpart[(size_t)(sl*B_ + b)*U_ + n];
        qadd_s[tid] = s;
        vv_s[tid]   = __ldg(&Vvec[n]);
    }

    const float* abase = values + (size_t)m0 * D_;
    const unsigned char* btiles = g_Bsw + (size_t)nb*NKC*32768;

    // fill stage: B 2048x16B linear (image pre-swizzled); A fp32 into 144B rows.
    #define STAGE_FILL(stg, kc) do {                                              \
        const unsigned char* bt = btiles + (size_t)(kc)*32768;                    \
        const uint32_t bdst = base + (stg)*STG_SZ + OFF_BQ;                       \
        _Pragma("unroll")                                                         \
        for (int i = 0; i < 4; i++) {                                             \
            int g = tid + i*512;                                                  \
            cp_async16(bdst + g*16, bt + (size_t)g*16);                           \
        }                                                                         \
        const uint32_t adst = base + (stg)*STG_SZ;                                \
        _Pragma("unroll")                                                         \
        for (int i = 0; i < 2; i++) {                                             \
            int g = tid + i*512;                                                  \
            int r = g >> 3, c = g & 7;                                            \
            cp_async16(adst + r*144 + c*16,                                       \
                       abase + (size_t)r*D_ + (kc)*32 + c*4);                     \
        }                                                                         \
    } while (0)

    // convert chunk in stage stg: fp32 staging -> bf16 hi/lo (swizzled rows)
    #define CONV(stg) do {                                                        \
        const char* fa = sm + (stg)*STG_SZ + r_cvt*144 + kq_cvt*32;               \
        float4 f0 = *(const float4*)fa;                                           \
        float4 f1 = *(const float4*)(fa + 16);                                    \
        unsigned h0,h1,h2,h3, l0,l1,l2,l3;                                        \
        split_pack(f0.x, f0.y, h0, l0);                                           \
        split_pack(f0.z, f0.w, h1, l1);                                           \
        split_pack(f1.x, f1.y, h2, l2);                                           \
        split_pack(f1.z, f1.w, h3, l3);                                           \
        const uint32_t ab = base + (stg)*STG_SZ + OFF_BFA + r_cvt*128;            \
        const int rs = r_cvt & 7;                                                 \
        STS128(ab + ((kq_cvt       ^ rs)*16), h0, h1, h2, h3);                    \
        STS128(ab + (((kq_cvt + 4) ^ rs)*16), l0, l1, l2, l3);                    \
    } while (0)

    float acc[2][8][4];
    #pragma unroll
    for (int i = 0; i < 2; i++)
        #pragma unroll
        for (int j = 0; j < 8; j++)
            #pragma unroll
            for (int q = 0; q < 4; q++) acc[i][j][q] = 0.f;

    const uint32_t sxs  = (uint32_t)(ln & 7) * 16;
    const uint32_t khfA = (uint32_t)(ln >> 4);
    const uint32_t khfB = (uint32_t)((ln >> 3) & 1);
    uint32_t rA[2], rB[4];
    #pragma unroll
    for (int mi = 0; mi < 2; mi++)
        rA[mi] = (uint32_t)(wm*32 + mi*16 + (ln & 15)) * 128;
    #pragma unroll
    for (int nt = 0; nt < 4; nt++)
        rB[nt] = (uint32_t)(wn*64 + nt*16 + (ln & 7) + ((ln >> 4) << 3)) * 128;

    const int r_cvt = tid >> 2, kq_cvt = tid & 3;

    // prologue: fill chunks 0,1; convert chunk 0
    STAGE_FILL(0, 0); CP_COMMIT();
    STAGE_FILL(1, 1); CP_COMMIT();
    CP_WAIT1();                      // chunk 0 fp32+B landed
    __syncthreads();
    CONV(0);                         // bf16A stage0 (visible after barrier in iter 0)

    int s3 = 0;                      // kc % 3
    for (int kc = 0; kc < NKC; kc++) {
        // wait for chunk kc+1's fill (committed at iter kc-1 / prologue), conv ahead
        if (kc + 1 < NKC) {
            CP_WAIT0();
            int c3 = s3 + 1; if (c3 >= 3) c3 -= 3;
            CONV(c3);                // conv chunk kc+1 into stage (kc+1)%3
        }
        __syncthreads();             // MMA(kc-1) readers done; conv/bf16A visible

        // fill chunk kc+2 (stage (kc+2)%3) -- WAR vs MMA(kc-1) cleared by barrier
        if (kc + 2 < NKC) {
            int f3 = s3 + 2; if (f3 >= 3) f3 -= 3;
            STAGE_FILL(f3, kc + 2); CP_COMMIT();
        }

        const uint32_t A0 = base + s3*STG_SZ + OFF_BFA;
        const uint32_t B0 = base + s3*STG_SZ + OFF_BQ;
        #pragma unroll
        for (int s = 0; s < 2; s++) {
            uint32_t ah[2][4], al[2][4], bfr[4][4];
            const uint32_t cAh = (((uint32_t)s*2 + khfA)     * 16) ^ sxs;
            const uint32_t cAl = (((uint32_t)s*2 + khfA + 4) * 16) ^ sxs;
            #pragma unroll
            for (int mi = 0; mi < 2; mi++) {
                LDSM4(ah[mi], A0 + rA[mi] + cAh);
                LDSM4(al[mi], A0 + rA[mi] + cAl);
            }
            const uint32_t cBh = (((uint32_t)s*2 + khfB)     * 16) ^ sxs;
            const uint32_t cBl = (((uint32_t)s*2 + khfB + 4) * 16) ^ sxs;
            #pragma unroll
            for (int nt = 0; nt < 4; nt++) LDSM4(bfr[nt], B0 + rB[nt] + cBh);
            #pragma unroll
            for (int mi = 0; mi < 2; mi++)
                #pragma unroll
                for (int nt = 0; nt < 4; nt++) {
                    MMA16816(acc[mi][2*nt],   ah[mi], bfr[nt][0], bfr[nt][1]); // hi*hi
                    MMA16816(acc[mi][2*nt+1], ah[mi], bfr[nt][2], bfr[nt][3]);
                    MMA16816(acc[mi][2*nt],   al[mi], bfr[nt][0], bfr[nt][1]); // lo*hi
                    MMA16816(acc[mi][2*nt+1], al[mi], bfr[nt][2], bfr[nt][3]);
                }
            #pragma unroll
            for (int nt = 0; nt < 4; nt++) LDSM4(bfr[nt], B0 + rB[nt] + cBl);
            #pragma unroll
            for (int mi = 0; mi < 2; mi++)
                #pragma unroll
                for (int nt = 0; nt < 4; nt++) {
                    MMA16816(acc[mi][2*nt],   ah[mi], bfr[nt][0], bfr[nt][1]); // hi*lo
                    MMA16816(acc[mi][2*nt+1], ah[mi], bfr[nt][2], bfr[nt][3]);
                }
        }
        if (++s3 >= 3) s3 -= 3;
    }

    // ---- epilogue: tanh(c + qadd)*V folded into per-row partials ----
    float racc[4] = {0.f, 0.f, 0.f, 0.f};
    #pragma unroll
    for (int mi = 0; mi < 2; mi++)
        #pragma unroll
        for (int nj = 0; nj < 8; nj++) {
            const int nc = wn*64 + nj*8 + 2*(ln & 3);
            const float q0 = qadd_s[nc],   v0 = vv_s[nc];
            const float q1 = qadd_s[nc+1], v1 = vv_s[nc+1];
            const float* d = acc[mi][nj];
            racc[mi*2]   += fast_tanh(d[0] + q0)*v0 + fast_tanh(d[1] + q1)*v1;
            racc[mi*2+1] += fast_tanh(d[2] + q0)*v0 + fast_tanh(d[3] + q1)*v1;
        }
    #pragma unroll
    for (int off = 1; off <= 2; off <<= 1)
        #pragma unroll
        for (int i = 0; i < 4; i++)
            racc[i] += __shfl_xor_sync(0xffffffffu, racc[i], off);

    if ((ln & 3) == 0) {
        #pragma unroll
        for (int mi = 0; mi < 2; mi++)
            #pragma unroll
            for (int h = 0; h < 2; h++) {
                const int row = wm*32 + mi*16 + (ln >> 2) + 8*h;
                red[row*4 + wn] = racc[mi*2 + h];
            }
    }
    __syncthreads();
    if (tid < 128)
        g_spart[(size_t)nb*M_ + m0 + tid] =
            red[tid*4] + red[tid*4+1] + red[tid*4+2] + red[tid*4+3];
}

// ---------------------------------------------------------------------------
// K3: softmax over T per batch (sums the 4 n-block score partials).
// ---------------------------------------------------------------------------
__global__ void softmax_kernel(float* __restrict__ out_w) {
    __shared__ float sh[32];
    __shared__ float bcast;
    const int b = blockIdx.x, t = threadIdx.x;
    const int lane = t & 31, wd = t >> 5;
    const size_t idx = (size_t)b*T_ + t;

    float s = g_spart[idx] + g_spart[M_ + idx] + g_spart[2*(size_t)M_ + idx]
            + g_spart[3*(size_t)M_ + idx];

    float m = s;
    #pragma unroll
    for (int o = 16; o; o >>= 1) m = fmaxf(m, __shfl_xor_sync(0xffffffffu, m, o));
    if (lane == 0) sh[wd] = m;
    __syncthreads();
    if (wd == 0) {
        float mm = sh[lane];
        #pragma unroll
        for (int o = 16; o; o >>= 1) mm = fmaxf(mm, __shfl_xor_sync(0xffffffffu, mm, o));
        if (lane == 0) bcast = mm;
    }
    __syncthreads();
    const float mx = bcast;

    float e = __expf(s - mx);
    float sum = e;
    #pragma unroll
    for (int o = 16; o; o >>= 1) sum += __shfl_xor_sync(0xffffffffu, sum, o);
    __syncthreads();
    if (lane == 0) sh[wd] = sum;
    __syncthreads();
    if (wd == 0) {
        float ss = sh[lane];
        #pragma unroll
        for (int o = 16; o; o >>= 1) ss += __shfl_xor_sync(0xffffffffu, ss, o);
        if (lane == 0) bcast = ss;
    }
    __syncthreads();
    out_w[idx] = e / bcast;
}

// ---------------------------------------------------------------------------
// K4: context partials over t-slices of 256; grid (8, 4, 32), 256 threads.
// ---------------------------------------------------------------------------
__global__ void context_part_kernel(const float* __restrict__ values,
                                    const float* __restrict__ w) {
    __shared__ float ws[256];
    const int dc = blockIdx.x, ts = blockIdx.y, b = blockIdx.z;
    const int d  = dc*256 + threadIdx.x;
    ws[threadIdx.x] = w[(size_t)b*T_ + ts*256 + threadIdx.x];
    __syncthreads();
    const float* vp = values + ((size_t)b*T_ + ts*256)*D_ + d;
    float acc = 0.f;
    #pragma unroll 8
    for (int t = 0; t < 256; t++)
        acc += ws[t] * vp[(size_t)t*D_];
    g_ctxpart[(size_t)(ts*B_ + b)*D_ + d] = acc;
}

__global__ void context_reduce_kernel(float* __restrict__ ctx) {
    const size_t i = (size_t)blockIdx.x*256 + threadIdx.x;
    ctx[i] = g_ctxpart[i] + g_ctxpart[(size_t)B_*D_ + i]
           + g_ctxpart[(size_t)2*B_*D_ + i] + g_ctxpart[(size_t)3*B_*D_ + i];
}

// ---------------------------------------------------------------------------
extern "C" void kernel_launch(void* const* d_in, const int* in_sizes, int n_in,
                              void* d_out, int out_size) {
    const float* query  = (const float*)d_in[0];
    const float* values = (const float*)d_in[1];
    const float* W1     = (const float*)d_in[2];
    const float* b1     = (const float*)d_in[3];
    const float* W2     = (const float*)d_in[4];
    const float* b2     = (const float*)d_in[5];
    const float* V      = (const float*)d_in[6];
    // bv (d_in[7]) shifts all scores equally: softmax-invariant, outputs unaffected.

    float* out = (float*)d_out;
    float* ctx = out;                   // (B, D)
    float* w   = out + B_*D_;           // (B, T, 1)

    cudaFuncSetAttribute(score_kernel, cudaFuncAttributeMaxDynamicSharedMemorySize, SMEM_REQ);

    w1split_kernel      <<<dim3(4, 64),    256>>>(W1);
    qproj_part_kernel   <<<dim3(B_, 8),    256>>>(query, W2, b2);
    score_kernel        <<<dim3(4, 256), 512, SMEM_REQ>>>(values, b1, V);
    softmax_kernel      <<<B_,             T_ >>>(w);
    context_part_kernel <<<dim3(8, 4, B_), 256>>>(values, w);
    context_reduce_kernel<<<(B_*D_)/256,   256>>>(ctx);
}

// round 14
// speedup vs baseline: 2.7809x; 1.8760x over previous
#include <cuda_runtime.h>
#include <cuda_fp16.h>
#include <cstdint>
#include <stddef.h>

#define B_  32
#define T_  1024
#define D_  2048
#define U_  1024
#define M_  (B_*T_)
#define NIT 32                 // 32 k-iters of 64 elems

// ---- score kernel dynamic smem layout (offsets from 1024-aligned base) ----
// stage = fp32A 34816 (128 x 272B) + f16A 16384 (128 x 128B) + B 32768 (256 x 128B)
#define STG_SZ    83968
#define OFF_F16A  34816
#define OFF_BQ    51200
#define OFF_QADD  167936       // 256 floats
#define OFF_VV    168960       // 256 floats
#define OFF_RED   169984       // 128x4 floats
#define SMEM_REQ  173056       // 172032 + align slack

// ---- scratch globals (no device allocs allowed) ----
__device__ unsigned char g_Bh[(size_t)4*NIT*32768];    // 4MB fp16 W1 image, pre-swizzled
__device__ float g_qpart[8*B_*U_];
__device__ float g_spart[4*M_];
__device__ float g_ctxpart[8*(size_t)B_*D_];

// ============================ helpers ============================
__device__ __forceinline__ uint32_t smem_u32(const void* p) {
    uint32_t a;
    asm("{ .reg .u64 t; cvta.to.shared.u64 t, %1; cvt.u32.u64 %0, t; }" : "=r"(a) : "l"(p));
    return a;
}
__device__ __forceinline__ float fast_tanh(float x) {
    float y; asm("tanh.approx.f32 %0, %1;" : "=f"(y) : "f"(x)); return y;
}
__device__ __forceinline__ unsigned pack_h2(float a, float b) {
    __half ha = __float2half_rn(a), hb = __float2half_rn(b);
    return (unsigned)__half_as_ushort(ha) | ((unsigned)__half_as_ushort(hb) << 16);
}
__device__ __forceinline__ void cp_async16(uint32_t dst, const void* src) {
    asm volatile("cp.async.cg.shared.global [%0], [%1], 16;" :: "r"(dst), "l"(src));
}
#define CP_COMMIT() asm volatile("cp.async.commit_group;" ::: "memory")
#define CP_WAIT0()  asm volatile("cp.async.wait_group 0;" ::: "memory")
#define STS128(addr, r0, r1, r2, r3) \
    asm volatile("st.shared.v4.b32 [%0], {%1,%2,%3,%4};" \
                 :: "r"(addr), "r"(r0), "r"(r1), "r"(r2), "r"(r3) : "memory")
#define LDSM4(r, addr) \
    asm volatile("ldmatrix.sync.aligned.m8n8.x4.shared.b16 {%0,%1,%2,%3}, [%4];" \
                 : "=r"((r)[0]), "=r"((r)[1]), "=r"((r)[2]), "=r"((r)[3]) : "r"(addr))
#define MMA16816(d, a, b0, b1) \
    asm volatile("mma.sync.aligned.m16n8k16.row.col.f32.f16.f16.f32 " \
                 "{%0,%1,%2,%3}, {%4,%5,%6,%7}, {%8,%9}, {%0,%1,%2,%3};" \
                 : "+f"((d)[0]), "+f"((d)[1]), "+f"((d)[2]), "+f"((d)[3]) \
                 : "r"((a)[0]), "r"((a)[1]), "r"((a)[2]), "r"((a)[3]), "r"(b0), "r"(b1))

// ---------------------------------------------------------------------------
// K0: W1 -> fp16 transposed image g_Bh[nb 4][it 32][256 n x 128B row]
// row n: k[it*64 .. +63] as fp16, 16B granules XOR-swizzled by (n&7).
// grid (4, 32), 256 threads.
// ---------------------------------------------------------------------------
__global__ void w1h_kernel(const float* __restrict__ W1) {
    const int nb = blockIdx.x, it = blockIdx.y, t = threadIdx.x;
    const int ng = nb*256 + t;
    unsigned char* dst = g_Bh + ((size_t)(nb*NIT + it)*256 + t)*128;
    const int sx = t & 7;
    #pragma unroll
    for (int g = 0; g < 8; g++) {          // granule = 8 k values = 4 h2 regs
        unsigned r[4];
        #pragma unroll
        for (int i = 0; i < 4; i++) {
            float a = __ldg(&W1[(size_t)(it*64 + g*8 + 2*i    )*U_ + ng]);
            float b = __ldg(&W1[(size_t)(it*64 + g*8 + 2*i + 1)*U_ + ng]);
            r[i] = pack_h2(a, b);
        }
        *(uint4*)(dst + ((g ^ sx)*16)) = make_uint4(r[0], r[1], r[2], r[3]);
    }
}

// ---------------------------------------------------------------------------
// K1: qproj partials: g_qpart[sl][b][u] = sum_{d in 256-slice} q[b,d]*W2[d,u] (+b2@sl0)
// ---------------------------------------------------------------------------
__global__ void qproj_part_kernel(const float* __restrict__ query,
                                  const float* __restrict__ W2,
                                  const float* __restrict__ b2) {
    const int b = blockIdx.x, sl = blockIdx.y;
    const int u4 = threadIdx.x;
    float4 acc = (sl == 0) ? *(const float4*)&b2[u4*4] : make_float4(0.f,0.f,0.f,0.f);
    const float* q = query + (size_t)b * D_;
    const int d0 = sl * 256;
    #pragma unroll 8
    for (int d = d0; d < d0 + 256; d++) {
        float  qd = __ldg(&q[d]);
        float4 w  = *(const float4*)&W2[(size_t)d*U_ + u4*4];
        acc.x += qd*w.x; acc.y += qd*w.y; acc.z += qd*w.z; acc.w += qd*w.w;
    }
    *(float4*)&g_qpart[(size_t)(sl*B_ + b)*U_ + u4*4] = acc;
}

// ---------------------------------------------------------------------------
// K2: fused fp16 HMMA GEMM + tanh + dot-V -> g_spart[nb][m]
// grid (4 nblk, 256 mblk), 512 threads (16 warps, 4m x 4n, warp tile 32x64).
// 2-stage double buffer, 64-k iters, ONE barrier per iter.
// RACE FIX: the A fp32 staging bytes each thread CONVerts are copied by that
// SAME thread's cp.asyncs, so its own wait_group covers them (cp.async
// completion is only self-visible pre-barrier).
// ---------------------------------------------------------------------------
__global__ __launch_bounds__(512, 1)
void score_kernel(const float* __restrict__ values,
                  const float* __restrict__ b1,
                  const float* __restrict__ Vvec) {
    extern __shared__ char smraw[];
    const uint32_t rb   = smem_u32(smraw);
    const uint32_t base = (rb + 1023u) & ~1023u;
    char* sm = smraw + (base - rb);

    const int tid = threadIdx.x;
    const int wid = tid >> 5, ln = tid & 31;
    const int wm  = wid >> 2, wn = wid & 3;
    const int nb  = blockIdx.x, mb = blockIdx.y;
    const int m0  = mb * 128, n0 = nb * 256;
    const int b   = m0 >> 10;

    float* qadd_s = (float*)(sm + OFF_QADD);
    float* vv_s   = (float*)(sm + OFF_VV);
    float* red    = (float*)(sm + OFF_RED);

    if (tid < 256) {
        const int n = n0 + tid;
        float s = __ldg(&b1[n]);
        #pragma unroll
        for (int sl = 0; sl < 8; sl++) s += g_qpart[(size_t)(sl*B_ + b)*U_ + n];
        qadd_s[tid] = s;
        vv_s[tid]   = __ldg(&Vvec[n]);
    }

    const float* abase = values + (size_t)m0 * D_;
    const unsigned char* btiles = g_Bh + (size_t)nb*NIT*32768;

    const int r_cvt = tid >> 2, q_cvt = tid & 3;

    // fill iter: B 2048x16B linear (pre-swizzled); A fp32: thread (r_cvt,q_cvt)
    // copies EXACTLY the 64B it will CONV (self-visibility after wait_group).
    #define STAGE_FILL(stg, it) do {                                              \
        const unsigned char* bt = btiles + (size_t)(it)*32768;                    \
        const uint32_t bdst = base + (stg)*STG_SZ + OFF_BQ;                       \
        _Pragma("unroll")                                                         \
        for (int i = 0; i < 4; i++) {                                             \
            int g = tid + i*512;                                                  \
            cp_async16(bdst + g*16, bt + (size_t)g*16);                           \
        }                                                                         \
        const uint32_t adst = base + (stg)*STG_SZ + r_cvt*272 + q_cvt*64;         \
        const float* asrc = abase + (size_t)r_cvt*D_ + (it)*64 + q_cvt*16;        \
        _Pragma("unroll")                                                         \
        for (int i = 0; i < 4; i++)                                               \
            cp_async16(adst + i*16, asrc + i*4);                                  \
    } while (0)

    // convert A(it) in stage stg: fp32 staging -> fp16 rows (swizzled granules)
    #define CONV(stg) do {                                                        \
        const char* fa = sm + (stg)*STG_SZ + r_cvt*272 + q_cvt*64;                \
        float4 f0 = *(const float4*)fa;                                           \
        float4 f1 = *(const float4*)(fa + 16);                                    \
        float4 f2 = *(const float4*)(fa + 32);                                    \
        float4 f3 = *(const float4*)(fa + 48);                                    \
        unsigned p0 = pack_h2(f0.x, f0.y), p1 = pack_h2(f0.z, f0.w);              \
        unsigned p2 = pack_h2(f1.x, f1.y), p3 = pack_h2(f1.z, f1.w);              \
        unsigned p4 = pack_h2(f2.x, f2.y), p5 = pack_h2(f2.z, f2.w);              \
        unsigned p6 = pack_h2(f3.x, f3.y), p7 = pack_h2(f3.z, f3.w);              \
        const uint32_t ab = base + (stg)*STG_SZ + OFF_F16A + r_cvt*128;           \
        const int rs = r_cvt & 7;                                                 \
        STS128(ab + (((2*q_cvt    ) ^ rs)*16), p0, p1, p2, p3);                   \
        STS128(ab + (((2*q_cvt + 1) ^ rs)*16), p4, p5, p6, p7);                   \
    } while (0)

    float acc[2][8][4];
    #pragma unroll
    for (int i = 0; i < 2; i++)
        #pragma unroll
        for (int j = 0; j < 8; j++)
            #pragma unroll
            for (int q = 0; q < 4; q++) acc[i][j][q] = 0.f;

    const uint32_t sxs  = (uint32_t)(ln & 7) * 16;
    const uint32_t khfA = (uint32_t)(ln >> 4);
    const uint32_t khfB = (uint32_t)((ln >> 3) & 1);
    uint32_t rA[2], rB[4];
    #pragma unroll
    for (int mi = 0; mi < 2; mi++)
        rA[mi] = (uint32_t)(wm*32 + mi*16 + (ln & 15)) * 128;
    #pragma unroll
    for (int nt = 0; nt < 4; nt++)
        rB[nt] = (uint32_t)(wn*64 + nt*16 + (ln & 7) + ((ln >> 4) << 3)) * 128;

    // prologue: fill iter 0 only
    STAGE_FILL(0, 0); CP_COMMIT();

    for (int it = 0; it < NIT; it++) {
        const int s = it & 1;
        CP_WAIT0();                  // this thread's fill(it) copies landed
        CONV(s);                     // reads ONLY self-copied bytes -> safe pre-barrier
        __syncthreads();             // f16A + B visible to all; MMA(it-1) readers done
        if (it + 1 < NIT) { STAGE_FILL(s ^ 1, it + 1); CP_COMMIT(); }

        const uint32_t A0 = base + s*STG_SZ + OFF_F16A;
        const uint32_t B0 = base + s*STG_SZ + OFF_BQ;
        #pragma unroll
        for (int ks = 0; ks < 4; ks++) {
            uint32_t ah[2][4], bfr[4][4];
            const uint32_t cA = (((uint32_t)ks*2 + khfA) * 16) ^ sxs;
            #pragma unroll
            for (int mi = 0; mi < 2; mi++) LDSM4(ah[mi], A0 + rA[mi] + cA);
            const uint32_t cB = (((uint32_t)ks*2 + khfB) * 16) ^ sxs;
            #pragma unroll
            for (int nt = 0; nt < 4; nt++) LDSM4(bfr[nt], B0 + rB[nt] + cB);
            #pragma unroll
            for (int mi = 0; mi < 2; mi++)
                #pragma unroll
                for (int nt = 0; nt < 4; nt++) {
                    MMA16816(acc[mi][2*nt],   ah[mi], bfr[nt][0], bfr[nt][1]);
                    MMA16816(acc[mi][2*nt+1], ah[mi], bfr[nt][2], bfr[nt][3]);
                }
        }
    }

    // ---- epilogue: tanh(c + qadd)*V folded into per-row partials ----
    float racc[4] = {0.f, 0.f, 0.f, 0.f};
    #pragma unroll
    for (int mi = 0; mi < 2; mi++)
        #pragma unroll
        for (int nj = 0; nj < 8; nj++) {
            const int nc = wn*64 + nj*8 + 2*(ln & 3);
            const float q0 = qadd_s[nc],   v0 = vv_s[nc];
            const float q1 = qadd_s[nc+1], v1 = vv_s[nc+1];
            const float* d = acc[mi][nj];
            racc[mi*2]   += fast_tanh(d[0] + q0)*v0 + fast_tanh(d[1] + q1)*v1;
            racc[mi*2+1] += fast_tanh(d[2] + q0)*v0 + fast_tanh(d[3] + q1)*v1;
        }
    #pragma unroll
    for (int off = 1; off <= 2; off <<= 1)
        #pragma unroll
        for (int i = 0; i < 4; i++)
            racc[i] += __shfl_xor_sync(0xffffffffu, racc[i], off);

    if ((ln & 3) == 0) {
        #pragma unroll
        for (int mi = 0; mi < 2; mi++)
            #pragma unroll
            for (int h = 0; h < 2; h++) {
                const int row = wm*32 + mi*16 + (ln >> 2) + 8*h;
                red[row*4 + wn] = racc[mi*2 + h];
            }
    }
    __syncthreads();
    if (tid < 128)
        g_spart[(size_t)nb*M_ + m0 + tid] =
            red[tid*4] + red[tid*4+1] + red[tid*4+2] + red[tid*4+3];
}

// ---------------------------------------------------------------------------
// K3: softmax over T per batch (sums the 4 n-block score partials).
// ---------------------------------------------------------------------------
__global__ void softmax_kernel(float* __restrict__ out_w) {
    __shared__ float sh[32];
    __shared__ float bcast;
    const int b = blockIdx.x, t = threadIdx.x;
    const int lane = t & 31, wd = t >> 5;
    const size_t idx = (size_t)b*T_ + t;

    float s = g_spart[idx] + g_spart[M_ + idx] + g_spart[2*(size_t)M_ + idx]
            + g_spart[3*(size_t)M_ + idx];

    float m = s;
    #pragma unroll
    for (int o = 16; o; o >>= 1) m = fmaxf(m, __shfl_xor_sync(0xffffffffu, m, o));
    if (lane == 0) sh[wd] = m;
    __syncthreads();
    if (wd == 0) {
        float mm = sh[lane];
        #pragma unroll
        for (int o = 16; o; o >>= 1) mm = fmaxf(mm, __shfl_xor_sync(0xffffffffu, mm, o));
        if (lane == 0) bcast = mm;
    }
    __syncthreads();
    const float mx = bcast;

    float e = __expf(s - mx);
    float sum = e;
    #pragma unroll
    for (int o = 16; o; o >>= 1) sum += __shfl_xor_sync(0xffffffffu, sum, o);
    __syncthreads();
    if (lane == 0) sh[wd] = sum;
    __syncthreads();
    if (wd == 0) {
        float ss = sh[lane];
        #pragma unroll
        for (int o = 16; o; o >>= 1) ss += __shfl_xor_sync(0xffffffffu, ss, o);
        if (lane == 0) bcast = ss;
    }
    __syncthreads();
    out_w[idx] = e / bcast;
}

// ---------------------------------------------------------------------------
// K4: context partials over t-slices of 128; grid (8, 8, 32), 256 threads.
// ---------------------------------------------------------------------------
__global__ void context_part_kernel(const float* __restrict__ values,
                                    const float* __restrict__ w) {
    __shared__ float ws[128];
    const int dc = blockIdx.x, ts = blockIdx.y, b = blockIdx.z;
    const int d  = dc*256 + threadIdx.x;
    if (threadIdx.x < 128)
        ws[threadIdx.x] = w[(size_t)b*T_ + ts*128 + threadIdx.x];
    __syncthreads();
    const float* vp = values + ((size_t)b*T_ + ts*128)*D_ + d;
    float acc = 0.f;
    #pragma unroll 8
    for (int t = 0; t < 128; t++)
        acc += ws[t] * vp[(size_t)t*D_];
    g_ctxpart[(size_t)(ts*B_ + b)*D_ + d] = acc;
}

__global__ void context_reduce_kernel(float* __restrict__ ctx) {
    const size_t i = (size_t)blockIdx.x*256 + threadIdx.x;
    float s = 0.f;
    #pragma unroll
    for (int ts = 0; ts < 8; ts++)
        s += g_ctxpart[(size_t)ts*B_*D_ + i];
    ctx[i] = s;
}

// ---------------------------------------------------------------------------
extern "C" void kernel_launch(void* const* d_in, const int* in_sizes, int n_in,
                              void* d_out, int out_size) {
    const float* query  = (const float*)d_in[0];
    const float* values = (const float*)d_in[1];
    const float* W1     = (const float*)d_in[2];
    const float* b1     = (const float*)d_in[3];
    const float* W2     = (const float*)d_in[4];
    const float* b2     = (const float*)d_in[5];
    const float* V      = (const float*)d_in[6];
    // bv (d_in[7]) shifts all scores equally: softmax-invariant, outputs unaffected.

    float* out = (float*)d_out;
    float* ctx = out;                   // (B, D)
    float* w   = out + B_*D_;           // (B, T, 1)

    cudaFuncSetAttribute(score_kernel, cudaFuncAttributeMaxDynamicSharedMemorySize, SMEM_REQ);

    w1h_kernel          <<<dim3(4, 32),    256>>>(W1);
    qproj_part_kernel   <<<dim3(B_, 8),    256>>>(query, W2, b2);
    score_kernel        <<<dim3(4, 256), 512, SMEM_REQ>>>(values, b1, V);
    softmax_kernel      <<<B_,             T_ >>>(w);
    context_part_kernel <<<dim3(8, 8, B_), 256>>>(values, w);
    context_reduce_kernel<<<(B_*D_)/256,   256>>>(ctx);
}

// round 15
// speedup vs baseline: 2.8534x; 1.0261x over previous
#include <cuda_runtime.h>
#include <cuda_fp16.h>
#include <cstdint>
#include <stddef.h>

#define B_  32
#define T_  1024
#define D_  2048
#define U_  1024
#define M_  (B_*T_)
#define NIT 32                 // 32 k-iters of 64 elems

// ---- score kernel dynamic smem layout (offsets from 1024-aligned base) ----
// stage = fp32A 34816 (128 x 272B) + f16A 16384 (128 x 128B) + B 32768 (256 x 128B)
#define STG_SZ    83968
#define OFF_F16A  34816
#define OFF_BQ    51200
#define OFF_QADD  167936       // 256 floats
#define OFF_VV    168960       // 256 floats
#define OFF_RED   169984       // 128x4 floats
#define SMEM_REQ  173056       // 172032 + align slack

// ---- scratch globals (no device allocs allowed) ----
__device__ unsigned char g_Bh[(size_t)4*NIT*32768];    // 4MB fp16 W1 image, pre-swizzled
__device__ float g_qpart[8*B_*U_];
__device__ float g_spart[4*M_];
__device__ float g_ctxpart[8*(size_t)B_*D_];

// ============================ helpers ============================
__device__ __forceinline__ uint32_t smem_u32(const void* p) {
    uint32_t a;
    asm("{ .reg .u64 t; cvta.to.shared.u64 t, %1; cvt.u32.u64 %0, t; }" : "=r"(a) : "l"(p));
    return a;
}
__device__ __forceinline__ float fast_tanh(float x) {
    float y; asm("tanh.approx.f32 %0, %1;" : "=f"(y) : "f"(x)); return y;
}
__device__ __forceinline__ unsigned pack_h2(float a, float b) {
    __half ha = __float2half_rn(a), hb = __float2half_rn(b);
    return (unsigned)__half_as_ushort(ha) | ((unsigned)__half_as_ushort(hb) << 16);
}
__device__ __forceinline__ void cp_async16(uint32_t dst, const void* src) {
    asm volatile("cp.async.cg.shared.global [%0], [%1], 16;" :: "r"(dst), "l"(src));
}
#define CP_COMMIT() asm volatile("cp.async.commit_group;" ::: "memory")
#define CP_WAIT0()  asm volatile("cp.async.wait_group 0;" ::: "memory")
#define STS128(addr, r0, r1, r2, r3) \
    asm volatile("st.shared.v4.b32 [%0], {%1,%2,%3,%4};" \
                 :: "r"(addr), "r"(r0), "r"(r1), "r"(r2), "r"(r3) : "memory")
#define LDSM4(r, addr) \
    asm volatile("ldmatrix.sync.aligned.m8n8.x4.shared.b16 {%0,%1,%2,%3}, [%4];" \
                 : "=r"((r)[0]), "=r"((r)[1]), "=r"((r)[2]), "=r"((r)[3]) : "r"(addr))
#define MMA16816(d, a, b0, b1) \
    asm volatile("mma.sync.aligned.m16n8k16.row.col.f32.f16.f16.f32 " \
                 "{%0,%1,%2,%3}, {%4,%5,%6,%7}, {%8,%9}, {%0,%1,%2,%3};" \
                 : "+f"((d)[0]), "+f"((d)[1]), "+f"((d)[2]), "+f"((d)[3]) \
                 : "r"((a)[0]), "r"((a)[1]), "r"((a)[2]), "r"((a)[3]), "r"(b0), "r"(b1))

// ---------------------------------------------------------------------------
// K0: W1 -> fp16 transposed image g_Bh[nb 4][it 32][256 n x 128B row]
// row n: k[it*64 .. +63] as fp16, 16B granules XOR-swizzled by (n&7).
// grid (4, 32), 256 threads.
// ---------------------------------------------------------------------------
__global__ void w1h_kernel(const float* __restrict__ W1) {
    const int nb = blockIdx.x, it = blockIdx.y, t = threadIdx.x;
    const int ng = nb*256 + t;
    unsigned char* dst = g_Bh + ((size_t)(nb*NIT + it)*256 + t)*128;
    const int sx = t & 7;
    #pragma unroll
    for (int g = 0; g < 8; g++) {          // granule = 8 k values = 4 h2 regs
        unsigned r[4];
        #pragma unroll
        for (int i = 0; i < 4; i++) {
            float a = __ldg(&W1[(size_t)(it*64 + g*8 + 2*i    )*U_ + ng]);
            float b = __ldg(&W1[(size_t)(it*64 + g*8 + 2*i + 1)*U_ + ng]);
            r[i] = pack_h2(a, b);
        }
        *(uint4*)(dst + ((g ^ sx)*16)) = make_uint4(r[0], r[1], r[2], r[3]);
    }
}

// ---------------------------------------------------------------------------
// K1: qproj partials, W2 read ONCE total (8MB, not 256MB).
// grid (8 u-tiles, 8 d-slices), 256 threads. Block: u-tile 128, d-slice 256,
// all 32 batches. Thread (u, b-half) accumulates 16 batches for one u.
// q slice staged [d][b]-transposed in smem for float4 broadcast reads.
// ---------------------------------------------------------------------------
__global__ void qproj_part_kernel(const float* __restrict__ query,
                                  const float* __restrict__ W2,
                                  const float* __restrict__ b2) {
    __shared__ float q_s[256][36];         // [d][b], row 144B (16B-aligned, bank-shifted)
    const int ut = blockIdx.x, sl = blockIdx.y;
    const int u  = ut*128 + (threadIdx.x & 127);
    const int bh = threadIdx.x >> 7;       // 0..1 -> batches bh*16..+15

    for (int i = threadIdx.x; i < 32*256; i += 256) {
        int bb = i >> 8, dd = i & 255;     // coalesced gmem read over dd
        q_s[dd][bb] = __ldg(&query[(size_t)bb*D_ + sl*256 + dd]);
    }
    __syncthreads();

    float acc[16];
    const float bias = (sl == 0) ? __ldg(&b2[u]) : 0.f;
    #pragma unroll
    for (int j = 0; j < 16; j++) acc[j] = bias;

    #pragma unroll 4
    for (int d = 0; d < 256; d++) {
        const float wv = __ldg(&W2[(size_t)(sl*256 + d)*U_ + u]);
        const float4* qr = (const float4*)&q_s[d][bh*16];
        float4 a = qr[0], bq = qr[1], c = qr[2], e = qr[3];
        acc[0]  += wv*a.x;  acc[1]  += wv*a.y;  acc[2]  += wv*a.z;  acc[3]  += wv*a.w;
        acc[4]  += wv*bq.x; acc[5]  += wv*bq.y; acc[6]  += wv*bq.z; acc[7]  += wv*bq.w;
        acc[8]  += wv*c.x;  acc[9]  += wv*c.y;  acc[10] += wv*c.z;  acc[11] += wv*c.w;
        acc[12] += wv*e.x;  acc[13] += wv*e.y;  acc[14] += wv*e.z;  acc[15] += wv*e.w;
    }
    #pragma unroll
    for (int j = 0; j < 16; j++)
        g_qpart[(size_t)(sl*B_ + bh*16 + j)*U_ + u] = acc[j];
}

// ---------------------------------------------------------------------------
// K2: fused fp16 HMMA GEMM + tanh + dot-V -> g_spart[nb][m]
// grid (4 nblk, 256 mblk), 512 threads (16 warps, 4m x 4n, warp tile 32x64).
// 2-stage double buffer, ONE barrier per iter; WAIT+CONV(it+1) run in the
// MIDDLE of MMA(it) (after 3 of 4 ks-blocks) so the tensor pipe never idles
// on the serial section. Stage discipline between barriers: reads stage s,
// writes stage s^1 only.
// ---------------------------------------------------------------------------
__global__ __launch_bounds__(512, 1)
void score_kernel(const float* __restrict__ values,
                  const float* __restrict__ b1,
                  const float* __restrict__ Vvec) {
    extern __shared__ char smraw[];
    const uint32_t rb   = smem_u32(smraw);
    const uint32_t base = (rb + 1023u) & ~1023u;
    char* sm = smraw + (base - rb);

    const int tid = threadIdx.x;
    const int wid = tid >> 5, ln = tid & 31;
    const int wm  = wid >> 2, wn = wid & 3;
    const int nb  = blockIdx.x, mb = blockIdx.y;
    const int m0  = mb * 128, n0 = nb * 256;
    const int b   = m0 >> 10;

    float* qadd_s = (float*)(sm + OFF_QADD);
    float* vv_s   = (float*)(sm + OFF_VV);
    float* red    = (float*)(sm + OFF_RED);

    if (tid < 256) {
        const int n = n0 + tid;
        float s = __ldg(&b1[n]);
        #pragma unroll
        for (int sl = 0; sl < 8; sl++) s += g_qpart[(size_t)(sl*B_ + b)*U_ + n];
        qadd_s[tid] = s;
        vv_s[tid]   = __ldg(&Vvec[n]);
    }

    const float* abase = values + (size_t)m0 * D_;
    const unsigned char* btiles = g_Bh + (size_t)nb*NIT*32768;

    const int r_cvt = tid >> 2, q_cvt = tid & 3;

    // fill iter: B 2048x16B linear (pre-swizzled); A fp32: thread (r_cvt,q_cvt)
    // copies EXACTLY the 64B it will CONV (self-visibility after wait_group).
    #define STAGE_FILL(stg, it) do {                                              \
        const unsigned char* bt = btiles + (size_t)(it)*32768;                    \
        const uint32_t bdst = base + (stg)*STG_SZ + OFF_BQ;                       \
        _Pragma("unroll")                                                         \
        for (int i = 0; i < 4; i++) {                                             \
            int g = tid + i*512;                                                  \
            cp_async16(bdst + g*16, bt + (size_t)g*16);                           \
        }                                                                         \
        const uint32_t adst = base + (stg)*STG_SZ + r_cvt*272 + q_cvt*64;         \
        const float* asrc = abase + (size_t)r_cvt*D_ + (it)*64 + q_cvt*16;        \
        _Pragma("unroll")                                                         \
        for (int i = 0; i < 4; i++)                                               \
            cp_async16(adst + i*16, asrc + i*4);                                  \
    } while (0)

    // convert A(it) in stage stg: fp32 staging -> fp16 rows (swizzled granules)
    #define CONV(stg) do {                                                        \
        const char* fa = sm + (stg)*STG_SZ + r_cvt*272 + q_cvt*64;                \
        float4 f0 = *(const float4*)fa;                                           \
        float4 f1 = *(const float4*)(fa + 16);                                    \
        float4 f2 = *(const float4*)(fa + 32);                                    \
        float4 f3 = *(const float4*)(fa + 48);                                    \
        unsigned p0 = pack_h2(f0.x, f0.y), p1 = pack_h2(f0.z, f0.w);              \
        unsigned p2 = pack_h2(f1.x, f1.y), p3 = pack_h2(f1.z, f1.w);              \
        unsigned p4 = pack_h2(f2.x, f2.y), p5 = pack_h2(f2.z, f2.w);              \
        unsigned p6 = pack_h2(f3.x, f3.y), p7 = pack_h2(f3.z, f3.w);              \
        const uint32_t ab = base + (stg)*STG_SZ + OFF_F16A + r_cvt*128;           \
        const int rs = r_cvt & 7;                                                 \
        STS128(ab + (((2*q_cvt    ) ^ rs)*16), p0, p1, p2, p3);                   \
        STS128(ab + (((2*q_cvt + 1) ^ rs)*16), p4, p5, p6, p7);                   \
    } while (0)

    float acc[2][8][4];
    #pragma unroll
    for (int i = 0; i < 2; i++)
        #pragma unroll
        for (int j = 0; j < 8; j++)
            #pragma unroll
            for (int q = 0; q < 4; q++) acc[i][j][q] = 0.f;

    const uint32_t sxs  = (uint32_t)(ln & 7) * 16;
    const uint32_t khfA = (uint32_t)(ln >> 4);
    const uint32_t khfB = (uint32_t)((ln >> 3) & 1);
    uint32_t rA[2], rB[4];
    #pragma unroll
    for (int mi = 0; mi < 2; mi++)
        rA[mi] = (uint32_t)(wm*32 + mi*16 + (ln & 15)) * 128;
    #pragma unroll
    for (int nt = 0; nt < 4; nt++)
        rB[nt] = (uint32_t)(wn*64 + nt*16 + (ln & 7) + ((ln >> 4) << 3)) * 128;

    // one ks-block of LDSM + MMA on stage addresses A0/B0
    #define KS_BLOCK(ks_) do {                                                    \
        uint32_t ah[2][4], bfr[4][4];                                             \
        const uint32_t cA = (((uint32_t)(ks_)*2 + khfA) * 16) ^ sxs;              \
        _Pragma("unroll")                                                         \
        for (int mi = 0; mi < 2; mi++) LDSM4(ah[mi], A0 + rA[mi] + cA);           \
        const uint32_t cB = (((uint32_t)(ks_)*2 + khfB) * 16) ^ sxs;              \
        _Pragma("unroll")                                                         \
        for (int nt = 0; nt < 4; nt++) LDSM4(bfr[nt], B0 + rB[nt] + cB);          \
        _Pragma("unroll")                                                         \
        for (int mi = 0; mi < 2; mi++)                                            \
            _Pragma("unroll")                                                     \
            for (int nt = 0; nt < 4; nt++) {                                      \
                MMA16816(acc[mi][2*nt],   ah[mi], bfr[nt][0], bfr[nt][1]);        \
                MMA16816(acc[mi][2*nt+1], ah[mi], bfr[nt][2], bfr[nt][3]);        \
            }                                                                     \
    } while (0)

    // prologue: fill iter 0; convert it before entering the loop
    STAGE_FILL(0, 0); CP_COMMIT();
    CP_WAIT0();
    CONV(0);

    for (int it = 0; it < NIT; it++) {
        const int s = it & 1;
        __syncthreads();             // f16A(s)+B(s) visible; MMA(it-1) readers done
        if (it + 1 < NIT) { STAGE_FILL(s ^ 1, it + 1); CP_COMMIT(); }

        const uint32_t A0 = base + s*STG_SZ + OFF_F16A;
        const uint32_t B0 = base + s*STG_SZ + OFF_BQ;
        KS_BLOCK(0);
        KS_BLOCK(1);
        KS_BLOCK(2);
        if (it + 1 < NIT) {
            CP_WAIT0();              // own A(it+1) copies landed (~1536 cyc slack)
            CONV(s ^ 1);             // writes stage s^1 only -> no WAR vs MMA(it)
        }
        KS_BLOCK(3);
    }

    // ---- epilogue: tanh(c + qadd)*V folded into per-row partials ----
    float racc[4] = {0.f, 0.f, 0.f, 0.f};
    #pragma unroll
    for (int mi = 0; mi < 2; mi++)
        #pragma unroll
        for (int nj = 0; nj < 8; nj++) {
            const int nc = wn*64 + nj*8 + 2*(ln & 3);
            const float q0 = qadd_s[nc],   v0 = vv_s[nc];
            const float q1 = qadd_s[nc+1], v1 = vv_s[nc+1];
            const float* d = acc[mi][nj];
            racc[mi*2]   += fast_tanh(d[0] + q0)*v0 + fast_tanh(d[1] + q1)*v1;
            racc[mi*2+1] += fast_tanh(d[2] + q0)*v0 + fast_tanh(d[3] + q1)*v1;
        }
    #pragma unroll
    for (int off = 1; off <= 2; off <<= 1)
        #pragma unroll
        for (int i = 0; i < 4; i++)
            racc[i] += __shfl_xor_sync(0xffffffffu, racc[i], off);

    if ((ln & 3) == 0) {
        #pragma unroll
        for (int mi = 0; mi < 2; mi++)
            #pragma unroll
            for (int h = 0; h < 2; h++) {
                const int row = wm*32 + mi*16 + (ln >> 2) + 8*h;
                red[row*4 + wn] = racc[mi*2 + h];
            }
    }
    __syncthreads();
    if (tid < 128)
        g_spart[(size_t)nb*M_ + m0 + tid] =
            red[tid*4] + red[tid*4+1] + red[tid*4+2] + red[tid*4+3];
}

// ---------------------------------------------------------------------------
// K3: softmax over T per batch (sums the 4 n-block score partials).
// ---------------------------------------------------------------------------
__global__ void softmax_kernel(float* __restrict__ out_w) {
    __shared__ float sh[32];
    __shared__ float bcast;
    const int b = blockIdx.x, t = threadIdx.x;
    const int lane = t & 31, wd = t >> 5;
    const size_t idx = (size_t)b*T_ + t;

    float s = g_spart[idx] + g_spart[M_ + idx] + g_spart[2*(size_t)M_ + idx]
            + g_spart[3*(size_t)M_ + idx];

    float m = s;
    #pragma unroll
    for (int o = 16; o; o >>= 1) m = fmaxf(m, __shfl_xor_sync(0xffffffffu, m, o));
    if (lane == 0) sh[wd] = m;
    __syncthreads();
    if (wd == 0) {
        float mm = sh[lane];
        #pragma unroll
        for (int o = 16; o; o >>= 1) mm = fmaxf(mm, __shfl_xor_sync(0xffffffffu, mm, o));
        if (lane == 0) bcast = mm;
    }
    __syncthreads();
    const float mx = bcast;

    float e = __expf(s - mx);
    float sum = e;
    #pragma unroll
    for (int o = 16; o; o >>= 1) sum += __shfl_xor_sync(0xffffffffu, sum, o);
    __syncthreads();
    if (lane == 0) sh[wd] = sum;
    __syncthreads();
    if (wd == 0) {
        float ss = sh[lane];
        #pragma unroll
        for (int o = 16; o; o >>= 1) ss += __shfl_xor_sync(0xffffffffu, ss, o);
        if (lane == 0) bcast = ss;
    }
    __syncthreads();
    out_w[idx] = e / bcast;
}

// ---------------------------------------------------------------------------
// K4: context partials over t-slices of 128; grid (8, 8, 32), 256 threads.
// ---------------------------------------------------------------------------
__global__ void context_part_kernel(const float* __restrict__ values,
                                    const float* __restrict__ w) {
    __shared__ float ws[128];
    const int dc = blockIdx.x, ts = blockIdx.y, b = blockIdx.z;
    const int d  = dc*256 + threadIdx.x;
    if (threadIdx.x < 128)
        ws[threadIdx.x] = w[(size_t)b*T_ + ts*128 + threadIdx.x];
    __syncthreads();
    const float* vp = values + ((size_t)b*T_ + ts*128)*D_ + d;
    float acc = 0.f;
    #pragma unroll 8
    for (int t = 0; t < 128; t++)
        acc += ws[t] * vp[(size_t)t*D_];
    g_ctxpart[(size_t)(ts*B_ + b)*D_ + d] = acc;
}

__global__ void context_reduce_kernel(float* __restrict__ ctx) {
    const size_t i = (size_t)blockIdx.x*256 + threadIdx.x;
    float s = 0.f;
    #pragma unroll
    for (int ts = 0; ts < 8; ts++)
        s += g_ctxpart[(size_t)ts*B_*D_ + i];
    ctx[i] = s;
}

// ---------------------------------------------------------------------------
extern "C" void kernel_launch(void* const* d_in, const int* in_sizes, int n_in,
                              void* d_out, int out_size) {
    const float* query  = (const float*)d_in[0];
    const float* values = (const float*)d_in[1];
    const float* W1     = (const float*)d_in[2];
    const float* b1     = (const float*)d_in[3];
    const float* W2     = (const float*)d_in[4];
    const float* b2     = (const float*)d_in[5];
    const float* V      = (const float*)d_in[6];
    // bv (d_in[7]) shifts all scores equally: softmax-invariant, outputs unaffected.

    float* out = (float*)d_out;
    float* ctx = out;                   // (B, D)
    float* w   = out + B_*D_;           // (B, T, 1)

    cudaFuncSetAttribute(score_kernel, cudaFuncAttributeMaxDynamicSharedMemorySize, SMEM_REQ);

    w1h_kernel          <<<dim3(4, 32),    256>>>(W1);
    qproj_part_kernel   <<<dim3(8, 8),     256>>>(query, W2, b2);
    score_kernel        <<<dim3(4, 256), 512, SMEM_REQ>>>(values, b1, V);
    softmax_kernel      <<<B_,             T_ >>>(w);
    context_part_kernel <<<dim3(8, 8, B_), 256>>>(values, w);
    context_reduce_kernel<<<(B_*D_)/256,   256>>>(ctx);
}

// round 17
// speedup vs baseline: 3.1104x; 1.0901x over previous
#include <cuda_runtime.h>
#include <cuda_fp16.h>
#include <cstdint>
#include <stddef.h>

#define B_  32
#define T_  1024
#define D_  2048
#define U_  1024
#define M_  (B_*T_)
#define NIT 32                 // 32 k-iters of 64 elems

// ---- score kernel dynamic smem layout (offsets from 1024-aligned base) ----
// B ring: 3 stages x 32768 @ 0 ; f16A: 2 stages x 16384 @ 98304
#define STG_B     32768
#define OFF_F16A  98304
#define OFF_QADD  131072       // 256 floats
#define OFF_VV    132096       // 256 floats
#define OFF_RED   133120       // 128x4 floats
#define SMEM_REQ  136192       // 135168 + align slack

// ---- scratch globals (no device allocs allowed) ----
__device__ unsigned char g_Bh[(size_t)4*NIT*32768];    // 4MB fp16 W1 image, pre-swizzled
__device__ float g_qpart[8*B_*U_];
__device__ float g_spart[4*M_];
__device__ float g_ctxpart[8*(size_t)B_*D_];

// ============================ helpers ============================
__device__ __forceinline__ uint32_t smem_u32(const void* p) {
    uint32_t a;
    asm("{ .reg .u64 t; cvta.to.shared.u64 t, %1; cvt.u32.u64 %0, t; }" : "=r"(a) : "l"(p));
    return a;
}
__device__ __forceinline__ float fast_tanh(float x) {
    float y; asm("tanh.approx.f32 %0, %1;" : "=f"(y) : "f"(x)); return y;
}
__device__ __forceinline__ unsigned pack_h2(float a, float b) {
    __half ha = __float2half_rn(a), hb = __float2half_rn(b);
    return (unsigned)__half_as_ushort(ha) | ((unsigned)__half_as_ushort(hb) << 16);
}
__device__ __forceinline__ void cp_async16(uint32_t dst, const void* src) {
    asm volatile("cp.async.cg.shared.global [%0], [%1], 16;" :: "r"(dst), "l"(src));
}
#define CP_COMMIT() asm volatile("cp.async.commit_group;" ::: "memory")
#define CP_WAIT2()  asm volatile("cp.async.wait_group 2;" ::: "memory")
#define CP_WAIT1()  asm volatile("cp.async.wait_group 1;" ::: "memory")
#define CP_WAIT0()  asm volatile("cp.async.wait_group 0;" ::: "memory")
#define STS128(addr, r0, r1, r2, r3) \
    asm volatile("st.shared.v4.b32 [%0], {%1,%2,%3,%4};" \
                 :: "r"(addr), "r"(r0), "r"(r1), "r"(r2), "r"(r3) : "memory")
#define LDSM4(r, addr) \
    asm volatile("ldmatrix.sync.aligned.m8n8.x4.shared.b16 {%0,%1,%2,%3}, [%4];" \
                 : "=r"((r)[0]), "=r"((r)[1]), "=r"((r)[2]), "=r"((r)[3]) : "r"(addr))
#define MMA16816(d, a, b0, b1) \
    asm volatile("mma.sync.aligned.m16n8k16.row.col.f32.f16.f16.f32 " \
                 "{%0,%1,%2,%3}, {%4,%5,%6,%7}, {%8,%9}, {%0,%1,%2,%3};" \
                 : "+f"((d)[0]), "+f"((d)[1]), "+f"((d)[2]), "+f"((d)[3]) \
                 : "r"((a)[0]), "r"((a)[1]), "r"((a)[2]), "r"((a)[3]), "r"(b0), "r"(b1))

// ---------------------------------------------------------------------------
// K0: W1 -> fp16 transposed image g_Bh[nb 4][it 32][256 n x 128B row]
// row n: k[it*64 .. +63] as fp16, 16B granules XOR-swizzled by (n&7).
// grid (4, 32), 256 threads.
// ---------------------------------------------------------------------------
__global__ void w1h_kernel(const float* __restrict__ W1) {
    const int nb = blockIdx.x, it = blockIdx.y, t = threadIdx.x;
    const int ng = nb*256 + t;
    unsigned char* dst = g_Bh + ((size_t)(nb*NIT + it)*256 + t)*128;
    const int sx = t & 7;
    #pragma unroll
    for (int g = 0; g < 8; g++) {          // granule = 8 k values = 4 h2 regs
        unsigned r[4];
        #pragma unroll
        for (int i = 0; i < 4; i++) {
            float a = __ldg(&W1[(size_t)(it*64 + g*8 + 2*i    )*U_ + ng]);
            float b = __ldg(&W1[(size_t)(it*64 + g*8 + 2*i + 1)*U_ + ng]);
            r[i] = pack_h2(a, b);
        }
        *(uint4*)(dst + ((g ^ sx)*16)) = make_uint4(r[0], r[1], r[2], r[3]);
    }
}

// ---------------------------------------------------------------------------
// K1: qproj partials, W2 read ONCE total (8MB, not 256MB).
// grid (8 u-tiles, 8 d-slices), 256 threads.
// ---------------------------------------------------------------------------
__global__ void qproj_part_kernel(const float* __restrict__ query,
                                  const float* __restrict__ W2,
                                  const float* __restrict__ b2) {
    __shared__ float q_s[256][36];         // [d][b], row bank-shifted
    const int ut = blockIdx.x, sl = blockIdx.y;
    const int u  = ut*128 + (threadIdx.x & 127);
    const int bh = threadIdx.x >> 7;       // 0..1 -> batches bh*16..+15

    for (int i = threadIdx.x; i < 32*256; i += 256) {
        int bb = i >> 8, dd = i & 255;
        q_s[dd][bb] = __ldg(&query[(size_t)bb*D_ + sl*256 + dd]);
    }
    __syncthreads();

    float acc[16];
    const float bias = (sl == 0) ? __ldg(&b2[u]) : 0.f;
    #pragma unroll
    for (int j = 0; j < 16; j++) acc[j] = bias;

    #pragma unroll 4
    for (int d = 0; d < 256; d++) {
        const float wv = __ldg(&W2[(size_t)(sl*256 + d)*U_ + u]);
        const float4* qr = (const float4*)&q_s[d][bh*16];
        float4 a = qr[0], bq = qr[1], c = qr[2], e = qr[3];
        acc[0]  += wv*a.x;  acc[1]  += wv*a.y;  acc[2]  += wv*a.z;  acc[3]  += wv*a.w;
        acc[4]  += wv*bq.x; acc[5]  += wv*bq.y; acc[6]  += wv*bq.z; acc[7]  += wv*bq.w;
        acc[8]  += wv*c.x;  acc[9]  += wv*c.y;  acc[10] += wv*c.z;  acc[11] += wv*c.w;
        acc[12] += wv*e.x;  acc[13] += wv*e.y;  acc[14] += wv*e.z;  acc[15] += wv*e.w;
    }
    #pragma unroll
    for (int j = 0; j < 16; j++)
        g_qpart[(size_t)(sl*B_ + bh*16 + j)*U_ + u] = acc[j];
}

// ---------------------------------------------------------------------------
// K2: fused fp16 HMMA GEMM + tanh + dot-V -> g_spart[nb][m]
// grid (4 nblk, 256 mblk), 512 threads (16 warps, 4m x 4n, warp tile 32x64).
// A: direct LDG float4 x4 -> regs -> convert -> STS (NO fp32 smem staging).
// B: 3-stage cp.async ring (2 iters of slack). ONE barrier per iter.
// ---------------------------------------------------------------------------
__global__ __launch_bounds__(512, 1)
void score_kernel(const float* __restrict__ values,
                  const float* __restrict__ b1,
                  const float* __restrict__ Vvec) {
    extern __shared__ char smraw[];
    const uint32_t rb   = smem_u32(smraw);
    const uint32_t base = (rb + 1023u) & ~1023u;
    char* sm = smraw + (base - rb);

    const int tid = threadIdx.x;
    const int wid = tid >> 5, ln = tid & 31;
    const int wm  = wid >> 2, wn = wid & 3;
    const int nb  = blockIdx.x, mb = blockIdx.y;
    const int m0  = mb * 128, n0 = nb * 256;
    const int b   = m0 >> 10;

    float* qadd_s = (float*)(sm + OFF_QADD);
    float* vv_s   = (float*)(sm + OFF_VV);
    float* red    = (float*)(sm + OFF_RED);

    if (tid < 256) {
        const int n = n0 + tid;
        float s = __ldg(&b1[n]);
        #pragma unroll
        for (int sl = 0; sl < 8; sl++) s += g_qpart[(size_t)(sl*B_ + b)*U_ + n];
        qadd_s[tid] = s;
        vv_s[tid]   = __ldg(&Vvec[n]);
    }

    const unsigned char* btiles = g_Bh + (size_t)nb*NIT*32768;

    const int r_cvt = tid >> 2, q_cvt = tid & 3;
    // this thread's A source row slice: row r_cvt, 16 k-elems at q_cvt*16
    const float* arow = values + (size_t)(m0 + r_cvt)*D_ + q_cvt*16;

    // fill B(it) into ring stage stg: 2048 x 16B linear (image pre-swizzled)
    #define FILL_B(stg, it) do {                                                  \
        const unsigned char* bt = btiles + (size_t)(it)*32768;                    \
        const uint32_t bdst = base + (stg)*STG_B;                                 \
        _Pragma("unroll")                                                         \
        for (int i = 0; i < 4; i++) {                                             \
            int g = tid + i*512;                                                  \
            cp_async16(bdst + g*16, bt + (size_t)g*16);                           \
        }                                                                         \
    } while (0)

    // LDG A(it) into staging regs (float4 x4 = this thread's 64B)
    float4 a_stg[4];
    #define LDG_A(it) do {                                                        \
        const float4* ap = (const float4*)(arow + (it)*64);                       \
        a_stg[0] = __ldg(ap);     a_stg[1] = __ldg(ap + 1);                       \
        a_stg[2] = __ldg(ap + 2); a_stg[3] = __ldg(ap + 3);                       \
    } while (0)

    // convert staging regs -> fp16 into f16A parity buffer pa (swizzled granules)
    #define CONV_REG(pa) do {                                                     \
        unsigned p0 = pack_h2(a_stg[0].x, a_stg[0].y), p1 = pack_h2(a_stg[0].z, a_stg[0].w); \
        unsigned p2 = pack_h2(a_stg[1].x, a_stg[1].y), p3 = pack_h2(a_stg[1].z, a_stg[1].w); \
        unsigned p4 = pack_h2(a_stg[2].x, a_stg[2].y), p5 = pack_h2(a_stg[2].z, a_stg[2].w); \
        unsigned p6 = pack_h2(a_stg[3].x, a_stg[3].y), p7 = pack_h2(a_stg[3].z, a_stg[3].w); \
        const uint32_t ab = base + OFF_F16A + (pa)*16384 + r_cvt*128;             \
        const int rs = r_cvt & 7;                                                 \
        STS128(ab + (((2*q_cvt    ) ^ rs)*16), p0, p1, p2, p3);                   \
        STS128(ab + (((2*q_cvt + 1) ^ rs)*16), p4, p5, p6, p7);                   \
    } while (0)

    float acc[2][8][4];
    #pragma unroll
    for (int i = 0; i < 2; i++)
        #pragma unroll
        for (int j = 0; j < 8; j++)
            #pragma unroll
            for (int q = 0; q < 4; q++) acc[i][j][q] = 0.f;

    const uint32_t sxs  = (uint32_t)(ln & 7) * 16;
    const uint32_t khfA = (uint32_t)(ln >> 4);
    const uint32_t khfB = (uint32_t)((ln >> 3) & 1);
    uint32_t rA[2], rB[4];
    #pragma unroll
    for (int mi = 0; mi < 2; mi++)
        rA[mi] = (uint32_t)(wm*32 + mi*16 + (ln & 15)) * 128;
    #pragma unroll
    for (int nt = 0; nt < 4; nt++)
        rB[nt] = (uint32_t)(wn*64 + nt*16 + (ln & 7) + ((ln >> 4) << 3)) * 128;

    #define KS_BLOCK(ks_) do {                                                    \
        uint32_t ah[2][4], bfr[4][4];                                             \
        const uint32_t cA = (((uint32_t)(ks_)*2 + khfA) * 16) ^ sxs;              \
        _Pragma("unroll")                                                         \
        for (int mi = 0; mi < 2; mi++) LDSM4(ah[mi], A0 + rA[mi] + cA);           \
        const uint32_t cB = (((uint32_t)(ks_)*2 + khfB) * 16) ^ sxs;              \
        _Pragma("unroll")                                                         \
        for (int nt = 0; nt < 4; nt++) LDSM4(bfr[nt], B0 + rB[nt] + cB);          \
        _Pragma("unroll")                                                         \
        for (int mi = 0; mi < 2; mi++)                                            \
            _Pragma("unroll")                                                     \
            for (int nt = 0; nt < 4; nt++) {                                      \
                MMA16816(acc[mi][2*nt],   ah[mi], bfr[nt][0], bfr[nt][1]);        \
                MMA16816(acc[mi][2*nt+1], ah[mi], bfr[nt][2], bfr[nt][3]);        \
            }                                                                     \
    } while (0)

    // prologue: A(0) via LDG -> conv into parity 0; B(0), B(1) in flight
    LDG_A(0);
    FILL_B(0, 0); CP_COMMIT();
    FILL_B(1, 1); CP_COMMIT();
    CONV_REG(0);                 // STS visible to all after barrier(0)

    int s3 = 0;                  // it % 3
    for (int it = 0; it < NIT; it++) {
        const int sa = it & 1;
        __syncthreads();         // f16A(sa)+B(s3) visible; MMA(it-1) readers done

        if (it + 1 < NIT) LDG_A(it + 1);          // regs; ~full iter of slack
        if (it + 2 < NIT) {
            int f3 = s3 + 2; if (f3 >= 3) f3 -= 3;
            FILL_B(f3, it + 2); CP_COMMIT();
            CP_WAIT2();          // B(it) landed (committed 2 iters ago)
        } else if (it + 1 < NIT) {
            CP_WAIT1();
        } else {
            CP_WAIT0();
        }

        const uint32_t A0 = base + OFF_F16A + sa*16384;
        const uint32_t B0 = base + s3*STG_B;
        KS_BLOCK(0);
        KS_BLOCK(1);
        KS_BLOCK(2);
        if (it + 1 < NIT) CONV_REG(sa ^ 1);       // writes other parity only
        KS_BLOCK(3);

        if (++s3 >= 3) s3 -= 3;
    }

    // ---- epilogue: tanh(c + qadd)*V folded into per-row partials ----
    float racc[4] = {0.f, 0.f, 0.f, 0.f};
    #pragma unroll
    for (int mi = 0; mi < 2; mi++)
        #pragma unroll
        for (int nj = 0; nj < 8; nj++) {
            const int nc = wn*64 + nj*8 + 2*(ln & 3);
            const float q0 = qadd_s[nc],   v0 = vv_s[nc];
            const float q1 = qadd_s[nc+1], v1 = vv_s[nc+1];
            const float* d = acc[mi][nj];
            racc[mi*2]   += fast_tanh(d[0] + q0)*v0 + fast_tanh(d[1] + q1)*v1;
            racc[mi*2+1] += fast_tanh(d[2] + q0)*v0 + fast_tanh(d[3] + q1)*v1;
        }
    #pragma unroll
    for (int off = 1; off <= 2; off <<= 1)
        #pragma unroll
        for (int i = 0; i < 4; i++)
            racc[i] += __shfl_xor_sync(0xffffffffu, racc[i], off);

    if ((ln & 3) == 0) {
        #pragma unroll
        for (int mi = 0; mi < 2; mi++)
            #pragma unroll
            for (int h = 0; h < 2; h++) {
                const int row = wm*32 + mi*16 + (ln >> 2) + 8*h;
                red[row*4 + wn] = racc[mi*2 + h];
            }
    }
    __syncthreads();
    if (tid < 128)
        g_spart[(size_t)nb*M_ + m0 + tid] =
            red[tid*4] + red[tid*4+1] + red[tid*4+2] + red[tid*4+3];
}

// ---------------------------------------------------------------------------
// K3: softmax over T per batch (sums the 4 n-block score partials).
// ---------------------------------------------------------------------------
__global__ void softmax_kernel(float* __restrict__ out_w) {
    __shared__ float sh[32];
    __shared__ float bcast;
    const int b = blockIdx.x, t = threadIdx.x;
    const int lane = t & 31, wd = t >> 5;
    const size_t idx = (size_t)b*T_ + t;

    float s = g_spart[idx] + g_spart[M_ + idx] + g_spart[2*(size_t)M_ + idx]
            + g_spart[3*(size_t)M_ + idx];

    float m = s;
    #pragma unroll
    for (int o = 16; o; o >>= 1) m = fmaxf(m, __shfl_xor_sync(0xffffffffu, m, o));
    if (lane == 0) sh[wd] = m;
    __syncthreads();
    if (wd == 0) {
        float mm = sh[lane];
        #pragma unroll
        for (int o = 16; o; o >>= 1) mm = fmaxf(mm, __shfl_xor_sync(0xffffffffu, mm, o));
        if (lane == 0) bcast = mm;
    }
    __syncthreads();
    const float mx = bcast;

    float e = __expf(s - mx);
    float sum = e;
    #pragma unroll
    for (int o = 16; o; o >>= 1) sum += __shfl_xor_sync(0xffffffffu, sum, o);
    __syncthreads();
    if (lane == 0) sh[wd] = sum;
    __syncthreads();
    if (wd == 0) {
        float ss = sh[lane];
        #pragma unroll
        for (int o = 16; o; o >>= 1) ss += __shfl_xor_sync(0xffffffffu, ss, o);
        if (lane == 0) bcast = ss;
    }
    __syncthreads();
    out_w[idx] = e / bcast;
}

// ---------------------------------------------------------------------------
// K4: context partials over t-slices of 128; grid (8, 8, 32), 256 threads.
// ---------------------------------------------------------------------------
__global__ void context_part_kernel(const float* __restrict__ values,
                                    const float* __restrict__ w) {
    __shared__ float ws[128];
    const int dc = blockIdx.x, ts = blockIdx.y, b = blockIdx.z;
    const int d  = dc*256 + threadIdx.x;
    if (threadIdx.x < 128)
        ws[threadIdx.x] = w[(size_t)b*T_ + ts*128 + threadIdx.x];
    __syncthreads();
    const float* vp = values + ((size_t)b*T_ + ts*128)*D_ + d;
    float acc = 0.f;
    #pragma unroll 8
    for (int t = 0; t < 128; t++)
        acc += ws[t] * vp[(size_t)t*D_];
    g_ctxpart[(size_t)(ts*B_ + b)*D_ + d] = acc;
}

__global__ void context_reduce_kernel(float* __restrict__ ctx) {
    const size_t i = (size_t)blockIdx.x*256 + threadIdx.x;
    float s = 0.f;
    #pragma unroll
    for (int ts = 0; ts < 8; ts++)
        s += g_ctxpart[(size_t)ts*B_*D_ + i];
    ctx[i] = s;
}

// ---------------------------------------------------------------------------
extern "C" void kernel_launch(void* const* d_in, const int* in_sizes, int n_in,
                              void* d_out, int out_size) {
    const float* query  = (const float*)d_in[0];
    const float* values = (const float*)d_in[1];
    const float* W1     = (const float*)d_in[2];
    const float* b1     = (const float*)d_in[3];
    const float* W2     = (const float*)d_in[4];
    const float* b2     = (const float*)d_in[5];
    const float* V      = (const float*)d_in[6];
    // bv (d_in[7]) shifts all scores equally: softmax-invariant, outputs unaffected.

    float* out = (float*)d_out;
    float* ctx = out;                   // (B, D)
    float* w   = out + B_*D_;           // (B, T, 1)

    cudaFuncSetAttribute(score_kernel, cudaFuncAttributeMaxDynamicSharedMemorySize, SMEM_REQ);

    w1h_kernel          <<<dim3(4, 32),    256>>>(W1);
    qproj_part_kernel   <<<dim3(8, 8),     256>>>(query, W2, b2);
    score_kernel        <<<dim3(4, 256), 512, SMEM_REQ>>>(values, b1, V);
    softmax_kernel      <<<B_,             T_ >>>(w);
    context_part_kernel <<<dim3(8, 8, B_), 256>>>(values, w);
    context_reduce_kernel<<<(B_*D_)/256,   256>>>(ctx);
}